// round 7
// baseline (speedup 1.0000x reference)
#include <cuda_runtime.h>

// mysoftmax: per-pixel softmax over C=19 + variance propagation through the
// squared softmax Jacobian.
//   p = softmax(mu)
//   sigma_out_i = p_i^2 * ( S + (1 - 2 p_i) * sigma_i ),  S = sum_j p_j^2 sigma_j
//
// d_out layout: [p (B*N*C floats), sigma_out (B*N*C floats)]
//
// R7: exp-first. e = exp(mu) is computed on the coalesced float4s right after
// the load and staged to smem (instead of mu); e and sigma float4s stay in
// registers end-to-end. Halves total MUFU work, removes the output-pass
// sigma re-read, and shortens the reduction's serial chain (no MUFU inside
// the loop). Smem round trip is reduced to the irreducible transpose.

static constexpr int C = 19;
static constexpr int PIX_PER_BLK = 128;
static constexpr int TILE  = PIX_PER_BLK * C;   // 2432 floats
static constexpr int TILE4 = TILE / 4;          // 608 float4
static constexpr int NITER = (TILE4 + PIX_PER_BLK - 1) / PIX_PER_BLK;  // 5

__global__ __launch_bounds__(PIX_PER_BLK)
void mysoftmax_kernel(const float* __restrict__ mu,
                      const float* __restrict__ sg,
                      float* __restrict__ out,
                      long long total_elems)   // B*N*C
{
    __shared__ __align__(16) float  se[TILE];    // exp(mu), staged for transpose
    __shared__ __align__(16) float  ssg[TILE];   // sigma,   staged for transpose
    __shared__ __align__(8)  float2 invS[PIX_PER_BLK];

    const int t = threadIdx.x;
    const long long base = (long long)blockIdx.x * TILE;

    // ---- coalesced load; exp applied immediately in registers ----
    const float4* __restrict__ mu4 = reinterpret_cast<const float4*>(mu + base);
    const float4* __restrict__ sg4 = reinterpret_cast<const float4*>(sg + base);
    float4* se4  = reinterpret_cast<float4*>(se);
    float4* ssg4 = reinterpret_cast<float4*>(ssg);

    float4 re[NITER];   // e = exp(mu), coalesced layout, lives in registers
    float4 rg[NITER];   // sigma,       coalesced layout, lives in registers

    #pragma unroll
    for (int i = 0; i < NITER; i++) {
        int idx = t + i * PIX_PER_BLK;
        if (idx < TILE4) {
            const float4 m = mu4[idx];
            const float4 g = sg4[idx];
            float4 e;
            e.x = __expf(m.x); e.y = __expf(m.y);
            e.z = __expf(m.z); e.w = __expf(m.w);
            re[i] = e;  rg[i] = g;
            se4[idx]  = e;
            ssg4[idx] = g;
        }
    }
    __syncthreads();

    // ---- per-pixel reduction (thread t <-> pixel t) ----
    // smem row stride 19 (odd) -> bank-conflict-free. Pure FMA chain (no MUFU).
    {
        const int row = t * C;
        float s0 = 0.f, s1 = 0.f;       // sum e_j
        float q0 = 0.f, q1 = 0.f;       // sum e_j^2 * sigma_j
        #pragma unroll
        for (int j = 0; j < C; j++) {
            const float e = se[row + j];
            const float g = ssg[row + j];
            if (j & 1) { s1 += e; q1 = fmaf(e * e, g, q1); }
            else       { s0 += e; q0 = fmaf(e * e, g, q0); }
        }
        const float inv = __frcp_rn(s0 + s1);
        invS[t] = make_float2(inv, (q0 + q1) * inv * inv);
    }
    __syncthreads();

    // ---- output pass: registers only (+ tiny invS LDS), straight to gmem ----
    float4* __restrict__ outp = reinterpret_cast<float4*>(out + base);
    float4* __restrict__ outs = reinterpret_cast<float4*>(out + total_elems + base);

    #pragma unroll
    for (int i = 0; i < NITER; i++) {
        int idx = t + i * PIX_PER_BLK;
        if (idx < TILE4) {
            const float4 e4 = re[i];
            const float4 g4 = rg[i];
            const unsigned e0 = (unsigned)idx * 4u;

            float4 p4, s4;
            {
                const float2 a = invS[(e0 + 0u) / 19u];
                const float p = e4.x * a.x;
                p4.x = p; s4.x = p * p * fmaf(1.0f - 2.0f * p, g4.x, a.y);
            }
            {
                const float2 a = invS[(e0 + 1u) / 19u];
                const float p = e4.y * a.x;
                p4.y = p; s4.y = p * p * fmaf(1.0f - 2.0f * p, g4.y, a.y);
            }
            {
                const float2 a = invS[(e0 + 2u) / 19u];
                const float p = e4.z * a.x;
                p4.z = p; s4.z = p * p * fmaf(1.0f - 2.0f * p, g4.z, a.y);
            }
            {
                const float2 a = invS[(e0 + 3u) / 19u];
                const float p = e4.w * a.x;
                p4.w = p; s4.w = p * p * fmaf(1.0f - 2.0f * p, g4.w, a.y);
            }

            outp[idx] = p4;
            outs[idx] = s4;
        }
    }
}

extern "C" void kernel_launch(void* const* d_in, const int* in_sizes, int n_in,
                              void* d_out, int out_size)
{
    const float* mu = (const float*)d_in[0];
    const float* sg = (const float*)d_in[1];
    float* out = (float*)d_out;

    const long long total_elems = (long long)in_sizes[0];        // B*N*C = 4,980,736
    const int n_pix = (int)(total_elems / C);                    // 262,144
    const int n_blocks = n_pix / PIX_PER_BLK;                    // 2048

    mysoftmax_kernel<<<n_blocks, PIX_PER_BLK>>>(mu, sg, out, total_elems);
}

// round 8
// speedup vs baseline: 1.0446x; 1.0446x over previous
#include <cuda_runtime.h>

// mysoftmax: per-pixel softmax over C=19 + variance propagation through the
// squared softmax Jacobian.
//   p = softmax(mu)
//   sigma_out_i = p_i^2 * ( S + (1 - 2 p_i) * sigma_i ),  S = sum_j p_j^2 sigma_j
//
// d_out layout: [p (B*N*C floats), sigma_out (B*N*C floats)]
//
// R8: dominant merge of R5 (best: regs 48, occ 54%) and R7 (exp-first).
// exp(mu) is computed ONCE on the coalesced float4s, staged to smem for the
// transpose, and kept in registers (re[5]) for the output pass. sigma is
// re-read from smem in the output pass (as in R5) so no rg[] register array.
// invS lookup uses the two-pixel-per-float4 property: 2 index computations
// and 2 LDS per float4 instead of 4.

static constexpr int C = 19;
static constexpr int PIX_PER_BLK = 128;
static constexpr int TILE  = PIX_PER_BLK * C;   // 2432 floats
static constexpr int TILE4 = TILE / 4;          // 608 float4
static constexpr int NITER = (TILE4 + PIX_PER_BLK - 1) / PIX_PER_BLK;  // 5

__global__ __launch_bounds__(PIX_PER_BLK)
void mysoftmax_kernel(const float* __restrict__ mu,
                      const float* __restrict__ sg,
                      float* __restrict__ out,
                      long long total_elems)   // B*N*C
{
    __shared__ __align__(16) float  se[TILE];    // exp(mu), staged for transpose
    __shared__ __align__(16) float  ssg[TILE];   // sigma,   staged for transpose
    __shared__ __align__(8)  float2 invS[PIX_PER_BLK];

    const int t = threadIdx.x;
    const long long base = (long long)blockIdx.x * TILE;

    // ---- coalesced load; exp applied immediately in registers ----
    const float4* __restrict__ mu4 = reinterpret_cast<const float4*>(mu + base);
    const float4* __restrict__ sg4 = reinterpret_cast<const float4*>(sg + base);
    float4* se4  = reinterpret_cast<float4*>(se);
    float4* ssg4 = reinterpret_cast<float4*>(ssg);

    float4 re[NITER];   // e = exp(mu), coalesced layout, lives in registers

    #pragma unroll
    for (int i = 0; i < NITER; i++) {
        int idx = t + i * PIX_PER_BLK;
        if (idx < TILE4) {
            const float4 m = mu4[idx];
            float4 e;
            e.x = __expf(m.x); e.y = __expf(m.y);
            e.z = __expf(m.z); e.w = __expf(m.w);
            re[i] = e;
            se4[idx]  = e;
            ssg4[idx] = sg4[idx];
        }
    }
    __syncthreads();

    // ---- per-pixel reduction (thread t <-> pixel t) ----
    // smem row stride 19 (odd) -> bank-conflict-free. Pure FMA chain, no MUFU.
    {
        const int row = t * C;
        float s0 = 0.f, s1 = 0.f;       // sum e_j
        float q0 = 0.f, q1 = 0.f;       // sum e_j^2 * sigma_j
        #pragma unroll
        for (int j = 0; j < C; j++) {
            const float e = se[row + j];
            const float g = ssg[row + j];
            if (j & 1) { s1 += e; q1 = fmaf(e * e, g, q1); }
            else       { s0 += e; q0 = fmaf(e * e, g, q0); }
        }
        const float inv = __frcp_rn(s0 + s1);
        invS[t] = make_float2(inv, (q0 + q1) * inv * inv);
    }
    __syncthreads();

    // ---- output pass: e from regs, sigma from smem, straight to gmem ----
    float4* __restrict__ outp = reinterpret_cast<float4*>(out + base);
    float4* __restrict__ outs = reinterpret_cast<float4*>(out + total_elems + base);

    #pragma unroll
    for (int i = 0; i < NITER; i++) {
        int idx = t + i * PIX_PER_BLK;
        if (idx < TILE4) {
            const float4 e4 = re[i];
            const float4 g4 = ssg4[idx];          // vectorized sigma re-read

            // a float4 (elements e0..e0+3) spans at most 2 pixels
            const unsigned e0 = (unsigned)idx * 4u;
            const unsigned pa = e0 / 19u;          // pixel of element e0
            const unsigned pb = (e0 + 3u) / 19u;   // pixel of element e0+3
            const float2 aa = invS[pa];
            const float2 ab = invS[pb];
            const unsigned lim = pb * 19u;         // first element of pixel pb

            float4 p4, s4;
            {
                const float2 a = (e0 + 0u < lim) ? aa : ab;
                const float p = e4.x * a.x;
                p4.x = p; s4.x = p * p * fmaf(1.0f - 2.0f * p, g4.x, a.y);
            }
            {
                const float2 a = (e0 + 1u < lim) ? aa : ab;
                const float p = e4.y * a.x;
                p4.y = p; s4.y = p * p * fmaf(1.0f - 2.0f * p, g4.y, a.y);
            }
            {
                const float2 a = (e0 + 2u < lim) ? aa : ab;
                const float p = e4.z * a.x;
                p4.z = p; s4.z = p * p * fmaf(1.0f - 2.0f * p, g4.z, a.y);
            }
            {
                const float p = e4.w * ab.x;       // last element: pixel pb
                p4.w = p; s4.w = p * p * fmaf(1.0f - 2.0f * p, g4.w, ab.y);
            }

            outp[idx] = p4;
            outs[idx] = s4;
        }
    }
}

extern "C" void kernel_launch(void* const* d_in, const int* in_sizes, int n_in,
                              void* d_out, int out_size)
{
    const float* mu = (const float*)d_in[0];
    const float* sg = (const float*)d_in[1];
    float* out = (float*)d_out;

    const long long total_elems = (long long)in_sizes[0];        // B*N*C = 4,980,736
    const int n_pix = (int)(total_elems / C);                    // 262,144
    const int n_blocks = n_pix / PIX_PER_BLK;                    // 2048

    mysoftmax_kernel<<<n_blocks, PIX_PER_BLK>>>(mu, sg, out, total_elems);
}